// round 1
// baseline (speedup 1.0000x reference)
#include <cuda_runtime.h>

// Problem constants
#define BB 512      // batch
#define SS 256      // set size
#define DD 64       // feature dim (K of GEMM)
#define HH 64       // n_hidden_sets
#define EE 8        // n_elements
#define HE 512      // HH*EE (N of GEMM)

// Kernel-1 tiling
#define SPLIT 2                 // split S across blocks
#define SPER (SS / SPLIT)       // 128 rows of S per block
#define TROWS 32                // rows per s-tile held in smem
#define NTILES (SPER / TROWS)   // 4
#define TM 8                    // rows per thread
#define THREADS1 256            // 4 row-groups x 64 h

#define THREADS2 512
#define BN_EPS 1e-5f

// Scratch: partial [split][b][h] sums (no dynamic alloc allowed)
__device__ float g_partial[SPLIT * BB * HH];

__device__ __forceinline__ float lrelu(float x) {
    // x>=0 -> x ; x<0 -> 0.01x   (max(x, 0.01x) is exact for both signs)
    return fmaxf(x, 0.01f * x);
}

// ---------------------------------------------------------------------------
// Kernel 1: fused GEMM + LeakyReLU + max over E + sum over S-slice
//   grid  = (BB, SPLIT), block = 256
//   smem  = Wc[64][512] (128KB) + Xtile[32][64] (8KB) + red[4][64] (1KB)
// ---------------------------------------------------------------------------
__global__ __launch_bounds__(THREADS1, 1)
void k1_gemm_pool(const float* __restrict__ X, const float* __restrict__ Wc) {
    extern __shared__ float sm[];
    float* ws  = sm;                       // [DD][HE]   k-major, matches Wc layout
    float* xs  = ws + DD * HE;             // [TROWS][DD]
    float* red = xs + TROWS * DD;          // [4][HH]

    const int b   = blockIdx.x;
    const int sp  = blockIdx.y;
    const int tid = threadIdx.x;
    const int h   = tid & 63;              // hidden-set index owned by this thread
    const int rg  = tid >> 6;              // row group 0..3

    // Cooperative load of Wc into smem (float4, coalesced)
    {
        const float4* src = reinterpret_cast<const float4*>(Wc);
        float4* dst = reinterpret_cast<float4*>(ws);
        #pragma unroll
        for (int i = tid; i < DD * HE / 4; i += THREADS1) dst[i] = src[i];
    }

    const float* xbase = X + ((size_t)b * SS + (size_t)sp * SPER) * DD;

    float hsum = 0.0f;   // sum over this block's S rows of max_e(lrelu(.))

    for (int t = 0; t < NTILES; t++) {
        __syncthreads();   // protects xs reuse; also fences Wc load on t==0
        {
            const float4* src = reinterpret_cast<const float4*>(xbase + t * TROWS * DD);
            float4* dst = reinterpret_cast<float4*>(xs);
            #pragma unroll
            for (int i = tid; i < TROWS * DD / 4; i += THREADS1) dst[i] = src[i];
        }
        __syncthreads();

        float acc[TM][EE];
        #pragma unroll
        for (int i = 0; i < TM; i++)
            #pragma unroll
            for (int e = 0; e < EE; e++) acc[i][e] = 0.0f;

        #pragma unroll 4
        for (int k = 0; k < DD; k++) {
            float xv[TM];
            #pragma unroll
            for (int i = 0; i < TM; i++)
                xv[i] = xs[(rg * TM + i) * DD + k];      // warp-broadcast
            float wv[EE];
            #pragma unroll
            for (int e = 0; e < EE; e++)
                wv[e] = ws[k * HE + e * HH + h];          // conflict-free (lane==bank)
            #pragma unroll
            for (int i = 0; i < TM; i++)
                #pragma unroll
                for (int e = 0; e < EE; e++)
                    acc[i][e] = fmaf(xv[i], wv[e], acc[i][e]);
        }

        // Epilogue: leaky -> max over E (in registers) -> accumulate sum over S
        #pragma unroll
        for (int i = 0; i < TM; i++) {
            float m = lrelu(acc[i][0]);
            #pragma unroll
            for (int e = 1; e < EE; e++) m = fmaxf(m, lrelu(acc[i][e]));
            hsum += m;
        }
    }

    // Reduce the 4 row-groups for each h
    red[rg * HH + h] = hsum;
    __syncthreads();
    if (tid < HH) {
        float v = red[tid] + red[HH + tid] + red[2 * HH + tid] + red[3 * HH + tid];
        g_partial[((size_t)sp * BB + b) * HH + tid] = v;
    }
}

// ---------------------------------------------------------------------------
// Kernel 2: fc1 + BatchNorm1d (training stats, two-pass) + LeakyReLU + fc2
//   single block, 512 threads (thread == batch element)
// ---------------------------------------------------------------------------
__global__ __launch_bounds__(THREADS2, 1)
void k2_head(const float* __restrict__ fc1_w, const float* __restrict__ fc1_b,
             const float* __restrict__ gamma, const float* __restrict__ beta,
             const float* __restrict__ fc2_w, const float* __restrict__ fc2_b,
             float* __restrict__ out) {
    extern __shared__ float sm[];
    float* Tsm  = sm;                       // [512][65]  padded vs bank conflicts
    float* wfc  = Tsm + BB * 65;            // [32][64]
    float* rsum = wfc + 32 * 64;            // [32]
    float* rvar = rsum + 32;                // [32]

    const int tid  = threadIdx.x;
    const int b    = tid;
    const int lane = tid & 31;

    // Stage T = partial0 + partial1 into padded smem (coalesced gmem reads)
    for (int i = tid; i < BB * HH; i += THREADS2) {
        float v = g_partial[i] + g_partial[BB * HH + i];
        Tsm[(i >> 6) * 65 + (i & 63)] = v;
    }
    for (int i = tid; i < 32 * 64; i += THREADS2) wfc[i] = fc1_w[i];
    if (tid < 32) { rsum[tid] = 0.0f; rvar[tid] = 0.0f; }
    __syncthreads();

    // fc1: u[j] = fc1_b[j] + sum_h T[b][h] * fc1_w[j][h]
    float u[32];
    #pragma unroll
    for (int j = 0; j < 32; j++) u[j] = __ldg(&fc1_b[j]);
    for (int h = 0; h < HH; h++) {
        float xv = Tsm[b * 65 + h];          // stride-65: conflict-free
        #pragma unroll
        for (int j = 0; j < 32; j++)
            u[j] = fmaf(wfc[j * 64 + h], xv, u[j]);   // warp-broadcast LDS
    }

    // Pass 1: batch mean per feature
    #pragma unroll
    for (int j = 0; j < 32; j++) {
        float v = u[j];
        #pragma unroll
        for (int o = 16; o; o >>= 1) v += __shfl_xor_sync(0xffffffffu, v, o);
        if (lane == 0) atomicAdd(&rsum[j], v);
    }
    __syncthreads();

    // Pass 2: centered values + biased variance (exactly matches reference)
    #pragma unroll
    for (int j = 0; j < 32; j++) {
        float d = u[j] - rsum[j] * (1.0f / (float)BB);
        u[j] = d;
        float v = d * d;
        #pragma unroll
        for (int o = 16; o; o >>= 1) v += __shfl_xor_sync(0xffffffffu, v, o);
        if (lane == 0) atomicAdd(&rvar[j], v);
    }
    __syncthreads();

    // Normalize, affine, LeakyReLU, fc2
    float acc = __ldg(&fc2_b[0]);
    #pragma unroll
    for (int j = 0; j < 32; j++) {
        float var = rvar[j] * (1.0f / (float)BB);
        float y = u[j] * rsqrtf(var + BN_EPS) * __ldg(&gamma[j]) + __ldg(&beta[j]);
        y = lrelu(y);
        acc = fmaf(y, __ldg(&fc2_w[j]), acc);
    }
    out[b] = acc;
}

// ---------------------------------------------------------------------------
extern "C" void kernel_launch(void* const* d_in, const int* in_sizes, int n_in,
                              void* d_out, int out_size) {
    const float* X     = (const float*)d_in[0];
    const float* Wc    = (const float*)d_in[1];
    const float* fc1_w = (const float*)d_in[2];
    const float* fc1_b = (const float*)d_in[3];
    const float* gamma = (const float*)d_in[4];
    const float* beta  = (const float*)d_in[5];
    const float* fc2_w = (const float*)d_in[6];
    const float* fc2_b = (const float*)d_in[7];
    float* out = (float*)d_out;

    const size_t sm1 = (size_t)(DD * HE + TROWS * DD + 4 * HH) * sizeof(float);       // ~140 KB
    const size_t sm2 = (size_t)(BB * 65 + 32 * 64 + 64) * sizeof(float);              // ~141 KB
    cudaFuncSetAttribute(k1_gemm_pool, cudaFuncAttributeMaxDynamicSharedMemorySize, (int)sm1);
    cudaFuncSetAttribute(k2_head,      cudaFuncAttributeMaxDynamicSharedMemorySize, (int)sm2);

    dim3 g1(BB, SPLIT);
    k1_gemm_pool<<<g1, THREADS1, sm1>>>(X, Wc);
    k2_head<<<1, THREADS2, sm2>>>(fc1_w, fc1_b, gamma, beta, fc2_w, fc2_b, out);
}

// round 3
// speedup vs baseline: 2.3109x; 2.3109x over previous
#include <cuda_runtime.h>
#include <cuda_bf16.h>
#include <cstdint>

// ---------------------------------------------------------------------------
// Problem constants
// ---------------------------------------------------------------------------
#define BB 512      // batch
#define SS 256      // set size
#define DD 64       // feature dim (K)
#define HH 64       // n_hidden_sets
#define EE 8        // n_elements
#define HE 512      // H*E (N of GEMM)
#define BN_EPS 1e-5f

// ---------------------------------------------------------------------------
// Device scratch (no dynamic allocation allowed)
// ---------------------------------------------------------------------------
__device__ __align__(16) char g_Bhi[HE * DD * 2];   // 64 KB, W^T bf16-hi, swizzled [n][k]
__device__ __align__(16) char g_Blo[HE * DD * 2];   // 64 KB, W^T bf16-lo
__device__ __align__(16) float g_u[BB * 32];        // fc1 output

__device__ __forceinline__ uint32_t smem_u32(const void* p) {
    uint32_t a;
    asm("{ .reg .u64 t; cvta.to.shared.u64 t, %1; cvt.u32.u64 %0, t; }" : "=r"(a) : "l"(p));
    return a;
}
__device__ __forceinline__ uint32_t swz(uint32_t off) {   // SW128: conflict-free ldmatrix
    return off ^ ((off >> 3) & 0x70);
}
__device__ __forceinline__ float lrelu(float x) { return fmaxf(x, 0.01f * x); }

__device__ __forceinline__ void ldsm_x4(uint32_t addr, uint32_t& r0, uint32_t& r1,
                                        uint32_t& r2, uint32_t& r3) {
    asm volatile("ldmatrix.sync.aligned.m8n8.x4.shared.b16 {%0,%1,%2,%3}, [%4];"
                 : "=r"(r0), "=r"(r1), "=r"(r2), "=r"(r3) : "r"(addr));
}
__device__ __forceinline__ void mma_bf16(float& c0, float& c1, float& c2, float& c3,
                                         uint32_t a0, uint32_t a1, uint32_t a2, uint32_t a3,
                                         uint32_t b0, uint32_t b1) {
    asm volatile("mma.sync.aligned.m16n8k16.row.col.f32.bf16.bf16.f32 "
                 "{%0,%1,%2,%3}, {%4,%5,%6,%7}, {%8,%9}, {%0,%1,%2,%3};"
                 : "+f"(c0), "+f"(c1), "+f"(c2), "+f"(c3)
                 : "r"(a0), "r"(a1), "r"(a2), "r"(a3), "r"(b0), "r"(b1));
}

// ---------------------------------------------------------------------------
// k0: build B = Wc^T in bf16 hi/lo, SW128-swizzled [n][k] images (128B rows)
// ---------------------------------------------------------------------------
__global__ void k0_prep(const float* __restrict__ Wc) {
    int idx = blockIdx.x * blockDim.x + threadIdx.x;   // 32768 = 512*64
    int n = idx >> 6, k = idx & 63;
    float w = Wc[k * HE + n];                           // B[n][k] = Wc[k][n]
    __nv_bfloat16 hi = __float2bfloat16(w);
    __nv_bfloat16 lo = __float2bfloat16(w - __bfloat162float(hi));
    uint32_t sw = swz((uint32_t)n * 128u + (uint32_t)k * 2u);
    *(__nv_bfloat16*)(g_Bhi + sw) = hi;
    *(__nv_bfloat16*)(g_Blo + sw) = lo;
}

// ---------------------------------------------------------------------------
// k1: per-batch-element fused GEMM (mma.sync bf16 3-pass split)
//     + LeakyReLU + max-over-E + sum-over-S + fc1
//   grid = 512 (CTA == batch element), 256 threads (8 warps)
//   warp w owns h-block [8w, 8w+8); B fragments live in registers.
// ---------------------------------------------------------------------------
#define K1_THREADS 256
#define SA_HI 0
#define SA_LO 32768
#define SB_HI 65536
#define SB_LO 131072
#define S_TSM 196608
#define SM_TOTAL (196608 + 256)

__global__ __launch_bounds__(K1_THREADS, 1)
void k1_gemm_pool(const float* __restrict__ X,
                  const float* __restrict__ fc1_w, const float* __restrict__ fc1_b) {
    extern __shared__ char smem[];
    const uint32_t sb = smem_u32(smem);
    const int tid = threadIdx.x;
    const int hb  = tid >> 5;          // warp id == h-block
    const int lane = tid & 31;
    const int b = blockIdx.x;

    // --- prologue: X[b] (256x64 fp32) -> A_hi/A_lo bf16, swizzled
    {
        const float4* xsrc = (const float4*)(X + (size_t)b * SS * DD);
        #pragma unroll
        for (int c = tid; c < 4096; c += K1_THREADS) {
            int row = c >> 4, k4 = (c & 15) << 2;
            float4 v = xsrc[c];
            __nv_bfloat16 h0 = __float2bfloat16(v.x), h1 = __float2bfloat16(v.y);
            __nv_bfloat16 h2 = __float2bfloat16(v.z), h3 = __float2bfloat16(v.w);
            __nv_bfloat16 l0 = __float2bfloat16(v.x - __bfloat162float(h0));
            __nv_bfloat16 l1 = __float2bfloat16(v.y - __bfloat162float(h1));
            __nv_bfloat16 l2 = __float2bfloat16(v.z - __bfloat162float(h2));
            __nv_bfloat16 l3 = __float2bfloat16(v.w - __bfloat162float(h3));
            uint32_t hi01 = ((uint32_t)__bfloat16_as_ushort(h1) << 16) | __bfloat16_as_ushort(h0);
            uint32_t hi23 = ((uint32_t)__bfloat16_as_ushort(h3) << 16) | __bfloat16_as_ushort(h2);
            uint32_t lo01 = ((uint32_t)__bfloat16_as_ushort(l1) << 16) | __bfloat16_as_ushort(l0);
            uint32_t lo23 = ((uint32_t)__bfloat16_as_ushort(l3) << 16) | __bfloat16_as_ushort(l2);
            uint32_t sw = swz((uint32_t)row * 128u + (uint32_t)k4 * 2u);
            *(uint2*)(smem + SA_HI + sw) = make_uint2(hi01, hi23);
            *(uint2*)(smem + SA_LO + sw) = make_uint2(lo01, lo23);
        }
    }
    // --- copy pre-swizzled B images (L2-hot broadcast)
    {
        const uint4* sh = (const uint4*)g_Bhi;
        const uint4* sl = (const uint4*)g_Blo;
        uint4* dh = (uint4*)(smem + SB_HI);
        uint4* dl = (uint4*)(smem + SB_LO);
        #pragma unroll
        for (int i = tid; i < 4096; i += K1_THREADS) { dh[i] = sh[i]; dl[i] = sl[i]; }
    }
    __syncthreads();

    // --- load all B fragments for this warp's h-block into registers.
    // bh[e][8]: regs [half*4+j]; for k-step ks: b0 = [.. (ks>>1)*4 + (ks&1)*2], b1 = +1
    uint32_t bh[EE][8], bl[EE][8];
    #pragma unroll
    for (int e = 0; e < EE; e++) {
        #pragma unroll
        for (int half = 0; half < 2; half++) {
            uint32_t off = (uint32_t)(e * 64 + hb * 8 + (lane & 7)) * 128u
                         + (uint32_t)half * 64u + (uint32_t)(lane >> 3) * 16u;
            uint32_t sw = swz(off);
            ldsm_x4(sb + SB_HI + sw, bh[e][half*4+0], bh[e][half*4+1],
                                      bh[e][half*4+2], bh[e][half*4+3]);
            ldsm_x4(sb + SB_LO + sw, bl[e][half*4+0], bl[e][half*4+1],
                                      bl[e][half*4+2], bl[e][half*4+3]);
        }
    }

    float sacc0 = 0.0f, sacc1 = 0.0f;

    #pragma unroll 1
    for (int mt = 0; mt < 16; mt++) {          // 16 m-tiles of 16 rows
        const int m0 = mt * 16;
        float c[EE][4];
        #pragma unroll
        for (int e = 0; e < EE; e++)
            #pragma unroll
            for (int i = 0; i < 4; i++) c[e][i] = 0.0f;

        #pragma unroll
        for (int ks = 0; ks < 4; ks++) {       // k-steps of 16
            uint32_t off = (uint32_t)(m0 + (lane & 15)) * 128u
                         + (uint32_t)ks * 32u + (uint32_t)(lane >> 4) * 16u;
            uint32_t sw = swz(off);
            uint32_t ah0, ah1, ah2, ah3, al0, al1, al2, al3;
            ldsm_x4(sb + SA_HI + sw, ah0, ah1, ah2, ah3);
            ldsm_x4(sb + SA_LO + sw, al0, al1, al2, al3);
            const int i0 = (ks >> 1) * 4 + (ks & 1) * 2;
            #pragma unroll
            for (int e = 0; e < EE; e++) {
                mma_bf16(c[e][0], c[e][1], c[e][2], c[e][3],
                         ah0, ah1, ah2, ah3, bh[e][i0], bh[e][i0+1]);   // hi*hi
                mma_bf16(c[e][0], c[e][1], c[e][2], c[e][3],
                         ah0, ah1, ah2, ah3, bl[e][i0], bl[e][i0+1]);   // hi*lo
                mma_bf16(c[e][0], c[e][1], c[e][2], c[e][3],
                         al0, al1, al2, al3, bh[e][i0], bh[e][i0+1]);   // lo*hi
            }
        }

        // epilogue: lrelu -> max over E (register) -> sum over this tile's rows
        float v0 = lrelu(c[0][0]), v1 = lrelu(c[0][1]);
        float v2 = lrelu(c[0][2]), v3 = lrelu(c[0][3]);
        #pragma unroll
        for (int e = 1; e < EE; e++) {
            v0 = fmaxf(v0, lrelu(c[e][0]));
            v1 = fmaxf(v1, lrelu(c[e][1]));
            v2 = fmaxf(v2, lrelu(c[e][2]));
            v3 = fmaxf(v3, lrelu(c[e][3]));
        }
        sacc0 += v0 + v2;   // rows lane/4 and lane/4+8, col h = hb*8 + (lane%4)*2
        sacc1 += v1 + v3;   // col h+1
    }

    // reduce over the 8 row-owner groups (threads sharing lane%4)
    #pragma unroll
    for (int o = 4; o <= 16; o <<= 1) {
        sacc0 += __shfl_xor_sync(0xffffffffu, sacc0, o);
        sacc1 += __shfl_xor_sync(0xffffffffu, sacc1, o);
    }
    float* tsm = (float*)(smem + S_TSM);
    if (lane < 4) {
        tsm[hb * 8 + lane * 2]     = sacc0;
        tsm[hb * 8 + lane * 2 + 1] = sacc1;
    }
    __syncthreads();

    // fused fc1: u[j] = fc1_b[j] + sum_h T[h] * fc1_w[j][h]
    if (tid < 32) {
        float u = __ldg(&fc1_b[tid]);
        #pragma unroll 8
        for (int h = 0; h < HH; h++)
            u = fmaf(tsm[h], __ldg(&fc1_w[tid * HH + h]), u);
        g_u[b * 32 + tid] = u;
    }
}

// ---------------------------------------------------------------------------
// k2: BatchNorm1d (training stats, two-pass, biased var) + LeakyReLU + fc2
// ---------------------------------------------------------------------------
__global__ __launch_bounds__(BB, 1)
void k2_head(const float* __restrict__ gamma, const float* __restrict__ beta,
             const float* __restrict__ fc2_w, const float* __restrict__ fc2_b,
             float* __restrict__ out) {
    __shared__ float rsum[32], rvar[32];
    const int tid = threadIdx.x, lane = tid & 31;

    float u[32];
    {
        const float4* src = (const float4*)(g_u + tid * 32);
        #pragma unroll
        for (int i = 0; i < 8; i++) {
            float4 v = src[i];
            u[4*i+0] = v.x; u[4*i+1] = v.y; u[4*i+2] = v.z; u[4*i+3] = v.w;
        }
    }
    if (tid < 32) { rsum[tid] = 0.0f; rvar[tid] = 0.0f; }
    __syncthreads();

    #pragma unroll
    for (int j = 0; j < 32; j++) {
        float v = u[j];
        #pragma unroll
        for (int o = 16; o; o >>= 1) v += __shfl_xor_sync(0xffffffffu, v, o);
        if (lane == 0) atomicAdd(&rsum[j], v);
    }
    __syncthreads();

    #pragma unroll
    for (int j = 0; j < 32; j++) {
        float d = u[j] - rsum[j] * (1.0f / (float)BB);
        u[j] = d;
        float v = d * d;
        #pragma unroll
        for (int o = 16; o; o >>= 1) v += __shfl_xor_sync(0xffffffffu, v, o);
        if (lane == 0) atomicAdd(&rvar[j], v);
    }
    __syncthreads();

    float a = __ldg(&fc2_b[0]);
    #pragma unroll
    for (int j = 0; j < 32; j++) {
        float var = rvar[j] * (1.0f / (float)BB);
        float y = u[j] * rsqrtf(var + BN_EPS) * __ldg(&gamma[j]) + __ldg(&beta[j]);
        a = fmaf(lrelu(y), __ldg(&fc2_w[j]), a);
    }
    out[tid] = a;
}

// ---------------------------------------------------------------------------
extern "C" void kernel_launch(void* const* d_in, const int* in_sizes, int n_in,
                              void* d_out, int out_size) {
    const float* X     = (const float*)d_in[0];
    const float* Wc    = (const float*)d_in[1];
    const float* fc1_w = (const float*)d_in[2];
    const float* fc1_b = (const float*)d_in[3];
    const float* gamma = (const float*)d_in[4];
    const float* beta  = (const float*)d_in[5];
    const float* fc2_w = (const float*)d_in[6];
    const float* fc2_b = (const float*)d_in[7];
    float* out = (float*)d_out;

    cudaFuncSetAttribute(k1_gemm_pool, cudaFuncAttributeMaxDynamicSharedMemorySize, SM_TOTAL);

    k0_prep<<<128, 256>>>(Wc);
    k1_gemm_pool<<<BB, K1_THREADS, SM_TOTAL>>>(X, fc1_w, fc1_b);
    k2_head<<<1, BB>>>(gamma, beta, fc2_w, fc2_b, out);
}

// round 4
// speedup vs baseline: 2.9072x; 1.2581x over previous
#include <cuda_runtime.h>
#include <cuda_fp16.h>
#include <cstdint>

// ---------------------------------------------------------------------------
// Problem constants
// ---------------------------------------------------------------------------
#define BB 512      // batch
#define SS 256      // set size
#define DD 64       // feature dim (K)
#define HH 64       // n_hidden_sets
#define EE 8        // n_elements
#define HE 512      // H*E (N of GEMM)
#define BN_EPS 1e-5f

// ---------------------------------------------------------------------------
// Device scratch (no dynamic allocation allowed)
// ---------------------------------------------------------------------------
__device__ __align__(16) char g_Bhi[HE * DD * 2];   // 64 KB, W^T fp16-hi, swizzled [n][k]
__device__ __align__(16) char g_Blo[HE * DD * 2];   // 64 KB, W^T fp16-lo (residual)
__device__ __align__(16) float g_u[BB * 32];        // fc1 output

__device__ __forceinline__ uint32_t smem_u32(const void* p) {
    uint32_t a;
    asm("{ .reg .u64 t; cvta.to.shared.u64 t, %1; cvt.u32.u64 %0, t; }" : "=r"(a) : "l"(p));
    return a;
}
__device__ __forceinline__ uint32_t swz(uint32_t off) {   // SW128: conflict-free ldmatrix
    return off ^ ((off >> 3) & 0x70);
}
__device__ __forceinline__ float lrelu(float x) { return fmaxf(x, 0.01f * x); }

__device__ __forceinline__ void ldsm_x4(uint32_t addr, uint32_t& r0, uint32_t& r1,
                                        uint32_t& r2, uint32_t& r3) {
    asm volatile("ldmatrix.sync.aligned.m8n8.x4.shared.b16 {%0,%1,%2,%3}, [%4];"
                 : "=r"(r0), "=r"(r1), "=r"(r2), "=r"(r3) : "r"(addr));
}
__device__ __forceinline__ void mma_fp16(float& c0, float& c1, float& c2, float& c3,
                                         uint32_t a0, uint32_t a1, uint32_t a2, uint32_t a3,
                                         uint32_t b0, uint32_t b1) {
    asm volatile("mma.sync.aligned.m16n8k16.row.col.f32.f16.f16.f32 "
                 "{%0,%1,%2,%3}, {%4,%5,%6,%7}, {%8,%9}, {%0,%1,%2,%3};"
                 : "+f"(c0), "+f"(c1), "+f"(c2), "+f"(c3)
                 : "r"(a0), "r"(a1), "r"(a2), "r"(a3), "r"(b0), "r"(b1));
}

// ---------------------------------------------------------------------------
// k0: build B = Wc^T in fp16 hi/lo, SW128-swizzled [n][k] images (128B rows)
// ---------------------------------------------------------------------------
__global__ void k0_prep(const float* __restrict__ Wc) {
    int idx = blockIdx.x * blockDim.x + threadIdx.x;   // 32768 = 512*64
    int n = idx >> 6, k = idx & 63;
    float w = Wc[k * HE + n];                           // B[n][k] = Wc[k][n]
    __half hi = __float2half_rn(w);
    __half lo = __float2half_rn(w - __half2float(hi));
    uint32_t sw = swz((uint32_t)n * 128u + (uint32_t)k * 2u);
    *(__half*)(g_Bhi + sw) = hi;
    *(__half*)(g_Blo + sw) = lo;
}

// ---------------------------------------------------------------------------
// k1: per-batch-element fused GEMM (mma.sync fp16, 2-pass W-split)
//     + LeakyReLU + max-over-E + sum-over-S + fc1
//   grid = 512 (CTA == batch element), 256 threads (8 warps)
//   warp w owns h-block [8w, 8w+8); B fragments live in registers.
// ---------------------------------------------------------------------------
#define K1_THREADS 256
#define SA    0
#define SB_HI 32768
#define SB_LO 98304
#define S_TSM 163840
#define SM_TOTAL (163840 + 256)

__global__ __launch_bounds__(K1_THREADS, 1)
void k1_gemm_pool(const float* __restrict__ X,
                  const float* __restrict__ fc1_w, const float* __restrict__ fc1_b) {
    extern __shared__ char smem[];
    const uint32_t sb = smem_u32(smem);
    const int tid = threadIdx.x;
    const int hb  = tid >> 5;          // warp id == h-block
    const int lane = tid & 31;
    const int b = blockIdx.x;

    // --- prologue: X[b] (256x64 fp32) -> single fp16 image, swizzled
    {
        const float4* xsrc = (const float4*)(X + (size_t)b * SS * DD);
        #pragma unroll
        for (int c = tid; c < 4096; c += K1_THREADS) {
            int row = c >> 4, k4 = (c & 15) << 2;
            float4 v = xsrc[c];
            __half h0 = __float2half_rn(v.x), h1 = __float2half_rn(v.y);
            __half h2 = __float2half_rn(v.z), h3 = __float2half_rn(v.w);
            uint32_t p01 = ((uint32_t)__half_as_ushort(h1) << 16) | __half_as_ushort(h0);
            uint32_t p23 = ((uint32_t)__half_as_ushort(h3) << 16) | __half_as_ushort(h2);
            uint32_t sw = swz((uint32_t)row * 128u + (uint32_t)k4 * 2u);
            *(uint2*)(smem + SA + sw) = make_uint2(p01, p23);
        }
    }
    // --- copy pre-swizzled B images (L2-hot broadcast)
    {
        const uint4* sh = (const uint4*)g_Bhi;
        const uint4* sl = (const uint4*)g_Blo;
        uint4* dh = (uint4*)(smem + SB_HI);
        uint4* dl = (uint4*)(smem + SB_LO);
        #pragma unroll
        for (int i = tid; i < 4096; i += K1_THREADS) { dh[i] = sh[i]; dl[i] = sl[i]; }
    }
    __syncthreads();

    // --- load all B fragments for this warp's h-block into registers.
    // bh[e][8]: regs [half*4+j]; for k-step ks: b0 = [.. (ks>>1)*4 + (ks&1)*2], b1 = +1
    uint32_t bh[EE][8], bl[EE][8];
    #pragma unroll
    for (int e = 0; e < EE; e++) {
        #pragma unroll
        for (int half = 0; half < 2; half++) {
            uint32_t off = (uint32_t)(e * 64 + hb * 8 + (lane & 7)) * 128u
                         + (uint32_t)half * 64u + (uint32_t)(lane >> 3) * 16u;
            uint32_t sw = swz(off);
            ldsm_x4(sb + SB_HI + sw, bh[e][half*4+0], bh[e][half*4+1],
                                      bh[e][half*4+2], bh[e][half*4+3]);
            ldsm_x4(sb + SB_LO + sw, bl[e][half*4+0], bl[e][half*4+1],
                                      bl[e][half*4+2], bl[e][half*4+3]);
        }
    }

    float sacc0 = 0.0f, sacc1 = 0.0f;

    #pragma unroll 1
    for (int mt = 0; mt < 16; mt++) {          // 16 m-tiles of 16 rows
        const int m0 = mt * 16;
        float c[EE][4];
        #pragma unroll
        for (int e = 0; e < EE; e++)
            #pragma unroll
            for (int i = 0; i < 4; i++) c[e][i] = 0.0f;

        #pragma unroll
        for (int ks = 0; ks < 4; ks++) {       // k-steps of 16
            uint32_t off = (uint32_t)(m0 + (lane & 15)) * 128u
                         + (uint32_t)ks * 32u + (uint32_t)(lane >> 4) * 16u;
            uint32_t sw = swz(off);
            uint32_t a0, a1, a2, a3;
            ldsm_x4(sb + SA + sw, a0, a1, a2, a3);
            const int i0 = (ks >> 1) * 4 + (ks & 1) * 2;
            #pragma unroll
            for (int e = 0; e < EE; e++) {
                mma_fp16(c[e][0], c[e][1], c[e][2], c[e][3],
                         a0, a1, a2, a3, bh[e][i0], bh[e][i0+1]);   // X * W_hi
                mma_fp16(c[e][0], c[e][1], c[e][2], c[e][3],
                         a0, a1, a2, a3, bl[e][i0], bl[e][i0+1]);   // X * W_lo
            }
        }

        // epilogue: lrelu -> max over E (register) -> sum over this tile's rows
        float v0 = lrelu(c[0][0]), v1 = lrelu(c[0][1]);
        float v2 = lrelu(c[0][2]), v3 = lrelu(c[0][3]);
        #pragma unroll
        for (int e = 1; e < EE; e++) {
            v0 = fmaxf(v0, lrelu(c[e][0]));
            v1 = fmaxf(v1, lrelu(c[e][1]));
            v2 = fmaxf(v2, lrelu(c[e][2]));
            v3 = fmaxf(v3, lrelu(c[e][3]));
        }
        sacc0 += v0 + v2;   // rows lane/4 and lane/4+8, col h = hb*8 + (lane%4)*2
        sacc1 += v1 + v3;   // col h+1
    }

    // reduce over the 8 row-owner groups (threads sharing lane%4)
    #pragma unroll
    for (int o = 4; o <= 16; o <<= 1) {
        sacc0 += __shfl_xor_sync(0xffffffffu, sacc0, o);
        sacc1 += __shfl_xor_sync(0xffffffffu, sacc1, o);
    }
    float* tsm = (float*)(smem + S_TSM);
    if (lane < 4) {
        tsm[hb * 8 + lane * 2]     = sacc0;
        tsm[hb * 8 + lane * 2 + 1] = sacc1;
    }
    __syncthreads();

    // fused fc1: u[j] = fc1_b[j] + sum_h T[h] * fc1_w[j][h]
    if (tid < 32) {
        float u = __ldg(&fc1_b[tid]);
        #pragma unroll 8
        for (int h = 0; h < HH; h++)
            u = fmaf(tsm[h], __ldg(&fc1_w[tid * HH + h]), u);
        g_u[b * 32 + tid] = u;
    }
}

// ---------------------------------------------------------------------------
// k2: BatchNorm1d (training stats, two-pass, biased var) + LeakyReLU + fc2
// ---------------------------------------------------------------------------
__global__ __launch_bounds__(BB, 1)
void k2_head(const float* __restrict__ gamma, const float* __restrict__ beta,
             const float* __restrict__ fc2_w, const float* __restrict__ fc2_b,
             float* __restrict__ out) {
    __shared__ float rsum[32], rvar[32];
    const int tid = threadIdx.x, lane = tid & 31;

    float u[32];
    {
        const float4* src = (const float4*)(g_u + tid * 32);
        #pragma unroll
        for (int i = 0; i < 8; i++) {
            float4 v = src[i];
            u[4*i+0] = v.x; u[4*i+1] = v.y; u[4*i+2] = v.z; u[4*i+3] = v.w;
        }
    }
    if (tid < 32) { rsum[tid] = 0.0f; rvar[tid] = 0.0f; }
    __syncthreads();

    #pragma unroll
    for (int j = 0; j < 32; j++) {
        float v = u[j];
        #pragma unroll
        for (int o = 16; o; o >>= 1) v += __shfl_xor_sync(0xffffffffu, v, o);
        if (lane == 0) atomicAdd(&rsum[j], v);
    }
    __syncthreads();

    #pragma unroll
    for (int j = 0; j < 32; j++) {
        float d = u[j] - rsum[j] * (1.0f / (float)BB);
        u[j] = d;
        float v = d * d;
        #pragma unroll
        for (int o = 16; o; o >>= 1) v += __shfl_xor_sync(0xffffffffu, v, o);
        if (lane == 0) atomicAdd(&rvar[j], v);
    }
    __syncthreads();

    float a = __ldg(&fc2_b[0]);
    #pragma unroll
    for (int j = 0; j < 32; j++) {
        float var = rvar[j] * (1.0f / (float)BB);
        float y = u[j] * rsqrtf(var + BN_EPS) * __ldg(&gamma[j]) + __ldg(&beta[j]);
        a = fmaf(lrelu(y), __ldg(&fc2_w[j]), a);
    }
    out[tid] = a;
}

// ---------------------------------------------------------------------------
extern "C" void kernel_launch(void* const* d_in, const int* in_sizes, int n_in,
                              void* d_out, int out_size) {
    const float* X     = (const float*)d_in[0];
    const float* Wc    = (const float*)d_in[1];
    const float* fc1_w = (const float*)d_in[2];
    const float* fc1_b = (const float*)d_in[3];
    const float* gamma = (const float*)d_in[4];
    const float* beta  = (const float*)d_in[5];
    const float* fc2_w = (const float*)d_in[6];
    const float* fc2_b = (const float*)d_in[7];
    float* out = (float*)d_out;

    cudaFuncSetAttribute(k1_gemm_pool, cudaFuncAttributeMaxDynamicSharedMemorySize, SM_TOTAL);

    k0_prep<<<128, 256>>>(Wc);
    k1_gemm_pool<<<BB, K1_THREADS, SM_TOTAL>>>(X, fc1_w, fc1_b);
    k2_head<<<1, BB>>>(gamma, beta, fc2_w, fc2_b, out);
}

// round 5
// speedup vs baseline: 4.5201x; 1.5548x over previous
#include <cuda_runtime.h>
#include <cuda_fp16.h>
#include <cstdint>

// ---------------------------------------------------------------------------
// Problem constants
// ---------------------------------------------------------------------------
#define BB 512      // batch
#define SS 256      // set size
#define DD 64      // feature dim (K)
#define HH 64       // n_hidden_sets
#define EE 8        // n_elements
#define HE 512      // H*E (N of GEMM)
#define BN_EPS 1e-5f

// ---------------------------------------------------------------------------
// Device scratch (no dynamic allocation allowed)
// ---------------------------------------------------------------------------
__device__ __align__(16) char g_B[HE * DD * 2];     // 64 KB, W^T fp16, swizzled [n][k]
__device__ __align__(16) float g_u[BB * 32];        // fc1 output

__device__ __forceinline__ uint32_t smem_u32(const void* p) {
    uint32_t a;
    asm("{ .reg .u64 t; cvta.to.shared.u64 t, %1; cvt.u32.u64 %0, t; }" : "=r"(a) : "l"(p));
    return a;
}
__device__ __forceinline__ uint32_t swz(uint32_t off) {   // SW128: conflict-free ldmatrix
    return off ^ ((off >> 3) & 0x70);
}
__device__ __forceinline__ float lrelu(float x) { return fmaxf(x, 0.01f * x); }

__device__ __forceinline__ void ldsm_x4(uint32_t addr, uint32_t& r0, uint32_t& r1,
                                        uint32_t& r2, uint32_t& r3) {
    asm volatile("ldmatrix.sync.aligned.m8n8.x4.shared.b16 {%0,%1,%2,%3}, [%4];"
                 : "=r"(r0), "=r"(r1), "=r"(r2), "=r"(r3) : "r"(addr));
}
__device__ __forceinline__ void mma_fp16(float& c0, float& c1, float& c2, float& c3,
                                         uint32_t a0, uint32_t a1, uint32_t a2, uint32_t a3,
                                         uint32_t b0, uint32_t b1) {
    asm volatile("mma.sync.aligned.m16n8k16.row.col.f32.f16.f16.f32 "
                 "{%0,%1,%2,%3}, {%4,%5,%6,%7}, {%8,%9}, {%0,%1,%2,%3};"
                 : "+f"(c0), "+f"(c1), "+f"(c2), "+f"(c3)
                 : "r"(a0), "r"(a1), "r"(a2), "r"(a3), "r"(b0), "r"(b1));
}

// ---------------------------------------------------------------------------
// k0: build B = Wc^T fp16, SW128-swizzled [n][k] image.  Coalesced reads:
//     consecutive threads read consecutive n (Wc is [k][n] row-major).
// ---------------------------------------------------------------------------
__global__ void k0_prep(const float* __restrict__ Wc) {
    int idx = blockIdx.x * blockDim.x + threadIdx.x;   // 32768 = 64*512
    int k = idx >> 9, n = idx & 511;
    float w = Wc[idx];                                  // Wc[k][n], coalesced
    uint32_t sw = swz((uint32_t)n * 128u + (uint32_t)k * 2u);
    *(__half*)(g_B + sw) = __float2half_rn(w);
}

// ---------------------------------------------------------------------------
// k1: per-batch-element fused GEMM (mma.sync fp16, single pass)
//     + LeakyReLU + max-over-E + sum-over-S + fc1
//   grid = 512 (CTA == batch element), 256 threads (8 warps), 2 CTAs/SM
//   warp w owns h-block [8w, 8w+8); B fragments live in registers.
// ---------------------------------------------------------------------------
#define K1_THREADS 256
#define SA    0
#define SB    32768
#define S_TSM 98304
#define SM_TOTAL (98304 + 256)

__global__ __launch_bounds__(K1_THREADS, 2)
void k1_gemm_pool(const float* __restrict__ X,
                  const float* __restrict__ fc1_w, const float* __restrict__ fc1_b) {
    extern __shared__ char smem[];
    const uint32_t sb = smem_u32(smem);
    const int tid = threadIdx.x;
    const int hb  = tid >> 5;          // warp id == h-block
    const int lane = tid & 31;
    const int b = blockIdx.x;

    // --- prologue: X[b] (256x64 fp32) -> fp16 image, swizzled
    {
        const float4* xsrc = (const float4*)(X + (size_t)b * SS * DD);
        #pragma unroll
        for (int c = tid; c < 4096; c += K1_THREADS) {
            int row = c >> 4, k4 = (c & 15) << 2;
            float4 v = xsrc[c];
            __half h0 = __float2half_rn(v.x), h1 = __float2half_rn(v.y);
            __half h2 = __float2half_rn(v.z), h3 = __float2half_rn(v.w);
            uint32_t p01 = ((uint32_t)__half_as_ushort(h1) << 16) | __half_as_ushort(h0);
            uint32_t p23 = ((uint32_t)__half_as_ushort(h3) << 16) | __half_as_ushort(h2);
            uint32_t sw = swz((uint32_t)row * 128u + (uint32_t)k4 * 2u);
            *(uint2*)(smem + SA + sw) = make_uint2(p01, p23);
        }
    }
    // --- copy pre-swizzled B image (L2-hot broadcast)
    {
        const uint4* s = (const uint4*)g_B;
        uint4* d = (uint4*)(smem + SB);
        #pragma unroll
        for (int i = tid; i < 4096; i += K1_THREADS) d[i] = s[i];
    }
    __syncthreads();

    // --- load all B fragments for this warp's h-block into registers.
    // bf[e][8]: regs [half*4+j]; for k-step ks: b0 = [.. (ks>>1)*4 + (ks&1)*2], b1 = +1
    uint32_t bf[EE][8];
    #pragma unroll
    for (int e = 0; e < EE; e++) {
        #pragma unroll
        for (int half = 0; half < 2; half++) {
            uint32_t off = (uint32_t)(e * 64 + hb * 8 + (lane & 7)) * 128u
                         + (uint32_t)half * 64u + (uint32_t)(lane >> 3) * 16u;
            uint32_t sw = swz(off);
            ldsm_x4(sb + SB + sw, bf[e][half*4+0], bf[e][half*4+1],
                                   bf[e][half*4+2], bf[e][half*4+3]);
        }
    }

    float sacc0 = 0.0f, sacc1 = 0.0f;

    #pragma unroll 1
    for (int mt = 0; mt < 16; mt++) {          // 16 m-tiles of 16 rows
        const int m0 = mt * 16;
        float c[EE][4];
        #pragma unroll
        for (int e = 0; e < EE; e++)
            #pragma unroll
            for (int i = 0; i < 4; i++) c[e][i] = 0.0f;

        #pragma unroll
        for (int ks = 0; ks < 4; ks++) {       // k-steps of 16
            uint32_t off = (uint32_t)(m0 + (lane & 15)) * 128u
                         + (uint32_t)ks * 32u + (uint32_t)(lane >> 4) * 16u;
            uint32_t sw = swz(off);
            uint32_t a0, a1, a2, a3;
            ldsm_x4(sb + SA + sw, a0, a1, a2, a3);
            const int i0 = (ks >> 1) * 4 + (ks & 1) * 2;
            #pragma unroll
            for (int e = 0; e < EE; e++)
                mma_fp16(c[e][0], c[e][1], c[e][2], c[e][3],
                         a0, a1, a2, a3, bf[e][i0], bf[e][i0+1]);
        }

        // epilogue: lrelu -> max over E (register) -> sum over this tile's rows
        float v0 = lrelu(c[0][0]), v1 = lrelu(c[0][1]);
        float v2 = lrelu(c[0][2]), v3 = lrelu(c[0][3]);
        #pragma unroll
        for (int e = 1; e < EE; e++) {
            v0 = fmaxf(v0, lrelu(c[e][0]));
            v1 = fmaxf(v1, lrelu(c[e][1]));
            v2 = fmaxf(v2, lrelu(c[e][2]));
            v3 = fmaxf(v3, lrelu(c[e][3]));
        }
        sacc0 += v0 + v2;   // rows lane/4 and lane/4+8, col h = hb*8 + (lane%4)*2
        sacc1 += v1 + v3;   // col h+1
    }

    // reduce over the 8 row-owner groups (threads sharing lane%4)
    #pragma unroll
    for (int o = 4; o <= 16; o <<= 1) {
        sacc0 += __shfl_xor_sync(0xffffffffu, sacc0, o);
        sacc1 += __shfl_xor_sync(0xffffffffu, sacc1, o);
    }
    float* tsm = (float*)(smem + S_TSM);
    if (lane < 4) {
        tsm[hb * 8 + lane * 2]     = sacc0;
        tsm[hb * 8 + lane * 2 + 1] = sacc1;
    }
    __syncthreads();

    // fused fc1: u[j] = fc1_b[j] + sum_h T[h] * fc1_w[j][h]
    if (tid < 32) {
        float u = __ldg(&fc1_b[tid]);
        #pragma unroll 8
        for (int h = 0; h < HH; h++)
            u = fmaf(tsm[h], __ldg(&fc1_w[tid * HH + h]), u);
        g_u[b * 32 + tid] = u;
    }
}

// ---------------------------------------------------------------------------
// k2: BatchNorm1d (training stats, two-pass, biased var) + LeakyReLU + fc2
// ---------------------------------------------------------------------------
__global__ __launch_bounds__(BB, 1)
void k2_head(const float* __restrict__ gamma, const float* __restrict__ beta,
             const float* __restrict__ fc2_w, const float* __restrict__ fc2_b,
             float* __restrict__ out) {
    __shared__ float rsum[32], rvar[32];
    const int tid = threadIdx.x, lane = tid & 31;

    float u[32];
    {
        const float4* src = (const float4*)(g_u + tid * 32);
        #pragma unroll
        for (int i = 0; i < 8; i++) {
            float4 v = src[i];
            u[4*i+0] = v.x; u[4*i+1] = v.y; u[4*i+2] = v.z; u[4*i+3] = v.w;
        }
    }
    if (tid < 32) { rsum[tid] = 0.0f; rvar[tid] = 0.0f; }
    __syncthreads();

    #pragma unroll
    for (int j = 0; j < 32; j++) {
        float v = u[j];
        #pragma unroll
        for (int o = 16; o; o >>= 1) v += __shfl_xor_sync(0xffffffffu, v, o);
        if (lane == 0) atomicAdd(&rsum[j], v);
    }
    __syncthreads();

    #pragma unroll
    for (int j = 0; j < 32; j++) {
        float d = u[j] - rsum[j] * (1.0f / (float)BB);
        u[j] = d;
        float v = d * d;
        #pragma unroll
        for (int o = 16; o; o >>= 1) v += __shfl_xor_sync(0xffffffffu, v, o);
        if (lane == 0) atomicAdd(&rvar[j], v);
    }
    __syncthreads();

    float a = __ldg(&fc2_b[0]);
    #pragma unroll
    for (int j = 0; j < 32; j++) {
        float var = rvar[j] * (1.0f / (float)BB);
        float y = u[j] * rsqrtf(var + BN_EPS) * __ldg(&gamma[j]) + __ldg(&beta[j]);
        a = fmaf(lrelu(y), __ldg(&fc2_w[j]), a);
    }
    out[tid] = a;
}

// ---------------------------------------------------------------------------
extern "C" void kernel_launch(void* const* d_in, const int* in_sizes, int n_in,
                              void* d_out, int out_size) {
    const float* X     = (const float*)d_in[0];
    const float* Wc    = (const float*)d_in[1];
    const float* fc1_w = (const float*)d_in[2];
    const float* fc1_b = (const float*)d_in[3];
    const float* gamma = (const float*)d_in[4];
    const float* beta  = (const float*)d_in[5];
    const float* fc2_w = (const float*)d_in[6];
    const float* fc2_b = (const float*)d_in[7];
    float* out = (float*)d_out;

    cudaFuncSetAttribute(k1_gemm_pool, cudaFuncAttributeMaxDynamicSharedMemorySize, SM_TOTAL);

    k0_prep<<<128, 256>>>(Wc);
    k1_gemm_pool<<<BB, K1_THREADS, SM_TOTAL>>>(X, fc1_w, fc1_b);
    k2_head<<<1, BB>>>(gamma, beta, fc2_w, fc2_b, out);
}

// round 6
// speedup vs baseline: 4.5597x; 1.0087x over previous
#include <cuda_runtime.h>
#include <cuda_fp16.h>
#include <cstdint>

// ---------------------------------------------------------------------------
// Problem constants
// ---------------------------------------------------------------------------
#define BB 512      // batch
#define SS 256      // set size
#define DD 64       // feature dim (K)
#define HH 64       // n_hidden_sets
#define EE 8        // n_elements
#define HE 512      // H*E (N of GEMM)
#define BN_EPS 1e-5f

#define NCTA 304          // ~2 per SM on GB300 (152 SMs); ticket loop absorbs mismatch
#define K1_THREADS 256

// smem layout (bytes)
#define SA     0                    // X fp16 image, 32 KB
#define SB     32768                // B fp16 image 64 KB | k2: US padded 67584 B
#define S_TSM  100352               // T[64] floats
#define S_WFC  100608               // fc1_w transposed [h][j] 8 KB
#define S_FB   108800               // fc1_b [32]
#define S_CTL  108928               // control ints
#define SM_TOTAL 108960

// ---------------------------------------------------------------------------
// Device scratch (no dynamic allocation allowed)
// ---------------------------------------------------------------------------
__device__ float g_u[BB * 32];      // fc1 output
__device__ int   g_ticket = 0;      // persistent work queue
__device__ int   g_done   = 0;      // completion counter

__device__ __forceinline__ uint32_t smem_u32(const void* p) {
    uint32_t a;
    asm("{ .reg .u64 t; cvta.to.shared.u64 t, %1; cvt.u32.u64 %0, t; }" : "=r"(a) : "l"(p));
    return a;
}
__device__ __forceinline__ uint32_t swz(uint32_t off) {   // SW128: conflict-free ldmatrix
    return off ^ ((off >> 3) & 0x70);
}
__device__ __forceinline__ float lrelu(float x) { return fmaxf(x, 0.01f * x); }

__device__ __forceinline__ void ldsm_x4(uint32_t addr, uint32_t& r0, uint32_t& r1,
                                        uint32_t& r2, uint32_t& r3) {
    asm volatile("ldmatrix.sync.aligned.m8n8.x4.shared.b16 {%0,%1,%2,%3}, [%4];"
                 : "=r"(r0), "=r"(r1), "=r"(r2), "=r"(r3) : "r"(addr));
}
__device__ __forceinline__ void mma_fp16(float& c0, float& c1, float& c2, float& c3,
                                         uint32_t a0, uint32_t a1, uint32_t a2, uint32_t a3,
                                         uint32_t b0, uint32_t b1) {
    asm volatile("mma.sync.aligned.m16n8k16.row.col.f32.f16.f16.f32 "
                 "{%0,%1,%2,%3}, {%4,%5,%6,%7}, {%8,%9}, {%0,%1,%2,%3};"
                 : "+f"(c0), "+f"(c1), "+f"(c2), "+f"(c3)
                 : "r"(a0), "r"(a1), "r"(a2), "r"(a3), "r"(b0), "r"(b1));
}

// ---------------------------------------------------------------------------
// Single persistent kernel: Wc prep + ticket loop (GEMM+pool+fc1) + last-CTA head
// ---------------------------------------------------------------------------
__global__ __launch_bounds__(K1_THREADS, 2)
void fused_all(const float* __restrict__ X, const float* __restrict__ Wc,
               const float* __restrict__ fc1_w, const float* __restrict__ fc1_b,
               const float* __restrict__ gamma, const float* __restrict__ beta,
               const float* __restrict__ fc2_w, const float* __restrict__ fc2_b,
               float* __restrict__ out) {
    extern __shared__ char smem[];
    const uint32_t sb = smem_u32(smem);
    const int tid  = threadIdx.x;
    const int hb   = tid >> 5;        // warp id == h-block
    const int lane = tid & 31;
    int* ctl = (int*)(smem + S_CTL);  // [0]=ticket bcast, [1]=last flag

    // ===== Phase A: build B = Wc^T fp16 SW128 [n][k] image in smem (once) =====
    // i over 16384 half2 (k-pairs): coalesced Wc reads; ~4-way smem store conflicts.
    for (int i = tid; i < 16384; i += K1_THREADS) {
        int kk = i >> 9;               // k = 2*kk
        int n  = i & 511;
        float w0 = Wc[(2 * kk)     * HE + n];
        float w1 = Wc[(2 * kk + 1) * HE + n];
        __half2 h = __floats2half2_rn(w0, w1);
        uint32_t sw = swz((uint32_t)n * 128u + (uint32_t)kk * 4u);
        *(__half2*)(smem + SB + sw) = h;
    }
    // stage fc1 weights transposed [h][j] + bias
    for (int i = tid; i < 32 * HH; i += K1_THREADS) {
        int j = i >> 6, h = i & 63;
        ((float*)(smem + S_WFC))[h * 32 + j] = fc1_w[i];
    }
    if (tid < 32) ((float*)(smem + S_FB))[tid] = fc1_b[tid];
    __syncthreads();

    // ===== load all B fragments for this warp's h-block into registers (once)
    uint32_t bf[EE][8];
    #pragma unroll
    for (int e = 0; e < EE; e++) {
        #pragma unroll
        for (int half = 0; half < 2; half++) {
            uint32_t off = (uint32_t)(e * 64 + hb * 8 + (lane & 7)) * 128u
                         + (uint32_t)half * 64u + (uint32_t)(lane >> 3) * 16u;
            uint32_t sw = swz(off);
            ldsm_x4(sb + SB + sw, bf[e][half*4+0], bf[e][half*4+1],
                                   bf[e][half*4+2], bf[e][half*4+3]);
        }
    }
    __syncthreads();

    // ===== Phase B: ticket loop over batch elements =====
    float* tsm = (float*)(smem + S_TSM);
    for (;;) {
        if (tid == 0) ctl[0] = atomicAdd(&g_ticket, 1);
        __syncthreads();
        const int b = ctl[0];
        if (b >= BB) break;

        // X[b] (256x64 fp32) -> fp16 image, swizzled
        {
            const float4* xsrc = (const float4*)(X + (size_t)b * SS * DD);
            #pragma unroll
            for (int c = tid; c < 4096; c += K1_THREADS) {
                int row = c >> 4, k4 = (c & 15) << 2;
                float4 v = xsrc[c];
                __half h0 = __float2half_rn(v.x), h1 = __float2half_rn(v.y);
                __half h2 = __float2half_rn(v.z), h3 = __float2half_rn(v.w);
                uint32_t p01 = ((uint32_t)__half_as_ushort(h1) << 16) | __half_as_ushort(h0);
                uint32_t p23 = ((uint32_t)__half_as_ushort(h3) << 16) | __half_as_ushort(h2);
                uint32_t sw = swz((uint32_t)row * 128u + (uint32_t)k4 * 2u);
                *(uint2*)(smem + SA + sw) = make_uint2(p01, p23);
            }
        }
        __syncthreads();

        float sacc0 = 0.0f, sacc1 = 0.0f;
        #pragma unroll 1
        for (int mt = 0; mt < 16; mt++) {          // 16 m-tiles of 16 rows
            const int m0 = mt * 16;
            float c[EE][4];
            #pragma unroll
            for (int e = 0; e < EE; e++)
                #pragma unroll
                for (int i = 0; i < 4; i++) c[e][i] = 0.0f;

            #pragma unroll
            for (int ks = 0; ks < 4; ks++) {       // k-steps of 16
                uint32_t off = (uint32_t)(m0 + (lane & 15)) * 128u
                             + (uint32_t)ks * 32u + (uint32_t)(lane >> 4) * 16u;
                uint32_t sw = swz(off);
                uint32_t a0, a1, a2, a3;
                ldsm_x4(sb + SA + sw, a0, a1, a2, a3);
                const int i0 = (ks >> 1) * 4 + (ks & 1) * 2;
                #pragma unroll
                for (int e = 0; e < EE; e++)
                    mma_fp16(c[e][0], c[e][1], c[e][2], c[e][3],
                             a0, a1, a2, a3, bf[e][i0], bf[e][i0+1]);
            }

            float v0 = lrelu(c[0][0]), v1 = lrelu(c[0][1]);
            float v2 = lrelu(c[0][2]), v3 = lrelu(c[0][3]);
            #pragma unroll
            for (int e = 1; e < EE; e++) {
                v0 = fmaxf(v0, lrelu(c[e][0]));
                v1 = fmaxf(v1, lrelu(c[e][1]));
                v2 = fmaxf(v2, lrelu(c[e][2]));
                v3 = fmaxf(v3, lrelu(c[e][3]));
            }
            sacc0 += v0 + v2;   // col h = hb*8 + (lane%4)*2
            sacc1 += v1 + v3;   // col h+1
        }

        #pragma unroll
        for (int o = 4; o <= 16; o <<= 1) {
            sacc0 += __shfl_xor_sync(0xffffffffu, sacc0, o);
            sacc1 += __shfl_xor_sync(0xffffffffu, sacc1, o);
        }
        if (lane < 4) {
            tsm[hb * 8 + lane * 2]     = sacc0;
            tsm[hb * 8 + lane * 2 + 1] = sacc1;
        }
        __syncthreads();

        // fused fc1 (conflict-free via transposed weights)
        if (tid < 32) {
            const float* wfc = (const float*)(smem + S_WFC);
            float u = ((const float*)(smem + S_FB))[tid];
            #pragma unroll 8
            for (int h = 0; h < HH; h++)
                u = fmaf(tsm[h], wfc[h * 32 + tid], u);
            g_u[b * 32 + tid] = u;
        }
        __syncthreads();   // tsm/SA safe to reuse; ctl[0] safe to overwrite
    }

    // ===== Phase C: last CTA runs BatchNorm + LeakyReLU + fc2 inline =====
    __threadfence();
    if (tid == 0) {
        int old = atomicAdd(&g_done, 1);
        ctl[1] = (old == NCTA - 1) ? 1 : 0;
    }
    __syncthreads();
    if (!ctl[1]) return;

    // stage g_u into padded smem US[b][j] stride 33 (conflict-free column sums)
    float* US = (float*)(smem + SB);
    for (int i = tid; i < BB * 32; i += K1_THREADS)
        US[(i >> 5) * 33 + (i & 31)] = g_u[i];
    float* PS   = (float*)(smem + SA);           // [8][32] partials
    float* MEAN = PS + 256;                      // [32]
    float* RS   = MEAN + 32;                     // [32]
    __syncthreads();

    const int j = tid & 31, g = tid >> 5;        // 8 groups x 32 features
    {
        float s = 0.0f;
        #pragma unroll 8
        for (int bb = g * 64; bb < g * 64 + 64; bb++) s += US[bb * 33 + j];
        PS[g * 32 + j] = s;
    }
    __syncthreads();
    if (tid < 32) {
        float m = 0.0f;
        #pragma unroll
        for (int g2 = 0; g2 < 8; g2++) m += PS[g2 * 32 + tid];
        MEAN[tid] = m * (1.0f / (float)BB);
    }
    __syncthreads();
    {
        float mu = MEAN[j], s = 0.0f;
        #pragma unroll 8
        for (int bb = g * 64; bb < g * 64 + 64; bb++) {
            float d = US[bb * 33 + j] - mu;
            s += d * d;
        }
        PS[g * 32 + j] = s;
    }
    __syncthreads();
    if (tid < 32) {
        float v = 0.0f;
        #pragma unroll
        for (int g2 = 0; g2 < 8; g2++) v += PS[g2 * 32 + tid];
        RS[tid] = rsqrtf(v * (1.0f / (float)BB) + BN_EPS);
    }
    __syncthreads();

    for (int bb = tid; bb < BB; bb += K1_THREADS) {
        float a = __ldg(&fc2_b[0]);
        #pragma unroll
        for (int j2 = 0; j2 < 32; j2++) {
            float y = (US[bb * 33 + j2] - MEAN[j2]) * RS[j2] * __ldg(&gamma[j2]) + __ldg(&beta[j2]);
            a = fmaf(lrelu(y), __ldg(&fc2_w[j2]), a);
        }
        out[bb] = a;
    }

    // reset counters for next graph replay
    if (tid == 0) { g_ticket = 0; g_done = 0; }
}

// ---------------------------------------------------------------------------
extern "C" void kernel_launch(void* const* d_in, const int* in_sizes, int n_in,
                              void* d_out, int out_size) {
    const float* X     = (const float*)d_in[0];
    const float* Wc    = (const float*)d_in[1];
    const float* fc1_w = (const float*)d_in[2];
    const float* fc1_b = (const float*)d_in[3];
    const float* gamma = (const float*)d_in[4];
    const float* beta  = (const float*)d_in[5];
    const float* fc2_w = (const float*)d_in[6];
    const float* fc2_b = (const float*)d_in[7];
    float* out = (float*)d_out;

    cudaFuncSetAttribute(fused_all, cudaFuncAttributeMaxDynamicSharedMemorySize, SM_TOTAL);
    fused_all<<<NCTA, K1_THREADS, SM_TOTAL>>>(X, Wc, fc1_w, fc1_b,
                                              gamma, beta, fc2_w, fc2_b, out);
}

// round 7
// speedup vs baseline: 4.6825x; 1.0269x over previous
#include <cuda_runtime.h>
#include <cuda_fp16.h>
#include <cstdint>

// ---------------------------------------------------------------------------
// Problem constants
// ---------------------------------------------------------------------------
#define BB 512      // batch
#define SS 256      // set size
#define DD 64       // feature dim (K)
#define HH 64       // n_hidden_sets
#define EE 8        // n_elements
#define HE 512      // H*E (N of GEMM)
#define BN_EPS 1e-5f

#define NCTA 304          // 2 per SM on GB300 (152 SMs)
#define K1_THREADS 256

#define NCHUNK 4          // 256 rows / 64
#define CH_ROWS 64
#define CH_F4   1024      // float4 per chunk

// smem layout (bytes)
#define S_BUF0 0                    // X fp16 chunk buf 0 (8 KB)
#define S_BUF1 8192                 // X fp16 chunk buf 1 (8 KB)
#define SB     16384                // B fp16 image 64 KB (dead after frag load) | Phase C: US
#define S_TSM  83968                // T[64] floats
#define S_WFC  84224                // fc1_w transposed [h][j] 8 KB
#define S_FB   92416                // fc1_b [32]
#define S_CTL  92544                // control ints
#define SM_TOTAL 92608

// ---------------------------------------------------------------------------
// Device scratch (no dynamic allocation allowed)
// ---------------------------------------------------------------------------
__device__ float g_u[BB * 32];      // fc1 output
__device__ int   g_ticket = 0;      // persistent work queue
__device__ int   g_done   = 0;      // completion counter

__device__ __forceinline__ uint32_t smem_u32(const void* p) {
    uint32_t a;
    asm("{ .reg .u64 t; cvta.to.shared.u64 t, %1; cvt.u32.u64 %0, t; }" : "=r"(a) : "l"(p));
    return a;
}
__device__ __forceinline__ uint32_t swz(uint32_t off) {   // SW128: conflict-free ldmatrix
    return off ^ ((off >> 3) & 0x70);
}
__device__ __forceinline__ float lrelu(float x) { return fmaxf(x, 0.01f * x); }

__device__ __forceinline__ void ldsm_x4(uint32_t addr, uint32_t& r0, uint32_t& r1,
                                        uint32_t& r2, uint32_t& r3) {
    asm volatile("ldmatrix.sync.aligned.m8n8.x4.shared.b16 {%0,%1,%2,%3}, [%4];"
                 : "=r"(r0), "=r"(r1), "=r"(r2), "=r"(r3) : "r"(addr));
}
__device__ __forceinline__ void mma_fp16(float& c0, float& c1, float& c2, float& c3,
                                         uint32_t a0, uint32_t a1, uint32_t a2, uint32_t a3,
                                         uint32_t b0, uint32_t b1) {
    asm volatile("mma.sync.aligned.m16n8k16.row.col.f32.f16.f16.f32 "
                 "{%0,%1,%2,%3}, {%4,%5,%6,%7}, {%8,%9}, {%0,%1,%2,%3};"
                 : "+f"(c0), "+f"(c1), "+f"(c2), "+f"(c3)
                 : "r"(a0), "r"(a1), "r"(a2), "r"(a3), "r"(b0), "r"(b1));
}

// convert 4 float4 (one chunk's share) -> swizzled fp16 buffer
__device__ __forceinline__ void cvt_sts_chunk(char* smem, int bufoff, int tid,
                                              const float4* v) {
    #pragma unroll
    for (int j = 0; j < 4; j++) {
        int cc = tid + j * 256;            // float4 idx within chunk
        int row = cc >> 4, k4 = (cc & 15) << 2;
        __half h0 = __float2half_rn(v[j].x), h1 = __float2half_rn(v[j].y);
        __half h2 = __float2half_rn(v[j].z), h3 = __float2half_rn(v[j].w);
        uint32_t p01 = ((uint32_t)__half_as_ushort(h1) << 16) | __half_as_ushort(h0);
        uint32_t p23 = ((uint32_t)__half_as_ushort(h3) << 16) | __half_as_ushort(h2);
        uint32_t sw = swz((uint32_t)row * 128u + (uint32_t)k4 * 2u);
        *(uint2*)(smem + bufoff + sw) = make_uint2(p01, p23);
    }
}

// ---------------------------------------------------------------------------
// Single persistent kernel, chunk-pipelined
// ---------------------------------------------------------------------------
__global__ __launch_bounds__(K1_THREADS, 2)
void fused_all(const float* __restrict__ X, const float* __restrict__ Wc,
               const float* __restrict__ fc1_w, const float* __restrict__ fc1_b,
               const float* __restrict__ gamma, const float* __restrict__ beta,
               const float* __restrict__ fc2_w, const float* __restrict__ fc2_b,
               float* __restrict__ out) {
    extern __shared__ char smem[];
    const uint32_t sb = smem_u32(smem);
    const int tid  = threadIdx.x;
    const int hb   = tid >> 5;        // warp id == h-block
    const int lane = tid & 31;
    int* ctl = (int*)(smem + S_CTL);  // [0],[1]=ticket slots (parity), [2]=last flag

    // ===== Phase A: build B = Wc^T fp16 SW128 [n][k] image in smem (once) =====
    for (int i = tid; i < 16384; i += K1_THREADS) {
        int kk = i >> 9;               // k = 2*kk
        int n  = i & 511;
        float w0 = Wc[(2 * kk)     * HE + n];
        float w1 = Wc[(2 * kk + 1) * HE + n];
        __half2 h = __floats2half2_rn(w0, w1);
        uint32_t sw = swz((uint32_t)n * 128u + (uint32_t)kk * 4u);
        *(__half2*)(smem + SB + sw) = h;
    }
    for (int i = tid; i < 32 * HH; i += K1_THREADS) {
        int j = i >> 6, h = i & 63;
        ((float*)(smem + S_WFC))[h * 32 + j] = fc1_w[i];
    }
    if (tid < 32) ((float*)(smem + S_FB))[tid] = fc1_b[tid];
    if (tid == 0) ctl[0] = atomicAdd(&g_ticket, 1);
    __syncthreads();

    // ===== load all B fragments for this warp's h-block into registers (once)
    uint32_t bf[EE][8];
    #pragma unroll
    for (int e = 0; e < EE; e++) {
        #pragma unroll
        for (int half = 0; half < 2; half++) {
            uint32_t off = (uint32_t)(e * 64 + hb * 8 + (lane & 7)) * 128u
                         + (uint32_t)half * 64u + (uint32_t)(lane >> 3) * 16u;
            uint32_t sw = swz(off);
            ldsm_x4(sb + SB + sw, bf[e][half*4+0], bf[e][half*4+1],
                                   bf[e][half*4+2], bf[e][half*4+3]);
        }
    }

    // ===== Phase B: chunk-pipelined ticket loop =====
    float* tsm = (float*)(smem + S_TSM);
    int b = ctl[0];        // first ticket (written before the barrier above)
    int bi = 0;
    int cur = 0;

    // preload chunk 0 of first b
    {
        const float4* xsrc = (const float4*)(X + (size_t)b * SS * DD);
        float4 v[4];
        #pragma unroll
        for (int j = 0; j < 4; j++) v[j] = xsrc[tid + j * 256];
        cvt_sts_chunk(smem, S_BUF0, tid, v);
    }
    __syncthreads();

    while (b < BB) {
        float sacc0 = 0.0f, sacc1 = 0.0f;

        #pragma unroll
        for (int ch = 0; ch < NCHUNK; ch++) {
            // prefetch next ticket early (consumed at ch==3; syncs in between)
            if (ch == 0 && tid == 0) ctl[(bi + 1) & 1] = atomicAdd(&g_ticket, 1);

            // ---- issue LDG for next chunk (latency hidden behind MMAs)
            bool have_next = true;
            const float4* nsrc = nullptr;
            if (ch < NCHUNK - 1) {
                nsrc = (const float4*)(X + (size_t)b * SS * DD) + (ch + 1) * CH_F4;
            } else {
                int nb = ctl[(bi + 1) & 1];
                if (nb < BB) nsrc = (const float4*)(X + (size_t)nb * SS * DD);
                else have_next = false;
            }
            float4 v[4];
            if (have_next) {
                #pragma unroll
                for (int j = 0; j < 4; j++) v[j] = nsrc[tid + j * 256];
            }

            // ---- MMA over current chunk (4 m-tiles of 16 rows)
            const int bufoff = cur ? S_BUF1 : S_BUF0;
            #pragma unroll
            for (int q = 0; q < 4; q++) {
                const int m0 = q * 16;   // local row within chunk buffer
                float c[EE][4];
                #pragma unroll
                for (int e = 0; e < EE; e++)
                    #pragma unroll
                    for (int i = 0; i < 4; i++) c[e][i] = 0.0f;

                #pragma unroll
                for (int ks = 0; ks < 4; ks++) {
                    uint32_t off = (uint32_t)(m0 + (lane & 15)) * 128u
                                 + (uint32_t)ks * 32u + (uint32_t)(lane >> 4) * 16u;
                    uint32_t sw = swz(off);
                    uint32_t a0, a1, a2, a3;
                    ldsm_x4(sb + bufoff + sw, a0, a1, a2, a3);
                    const int i0 = (ks >> 1) * 4 + (ks & 1) * 2;
                    #pragma unroll
                    for (int e = 0; e < EE; e++)
                        mma_fp16(c[e][0], c[e][1], c[e][2], c[e][3],
                                 a0, a1, a2, a3, bf[e][i0], bf[e][i0+1]);
                }

                float v0 = lrelu(c[0][0]), v1 = lrelu(c[0][1]);
                float v2 = lrelu(c[0][2]), v3 = lrelu(c[0][3]);
                #pragma unroll
                for (int e = 1; e < EE; e++) {
                    v0 = fmaxf(v0, lrelu(c[e][0]));
                    v1 = fmaxf(v1, lrelu(c[e][1]));
                    v2 = fmaxf(v2, lrelu(c[e][2]));
                    v3 = fmaxf(v3, lrelu(c[e][3]));
                }
                sacc0 += v0 + v2;   // col h = hb*8 + (lane%4)*2
                sacc1 += v1 + v3;   // col h+1
            }

            // ---- convert + store next chunk into the other buffer
            if (have_next) cvt_sts_chunk(smem, cur ? S_BUF0 : S_BUF1, tid, v);
            __syncthreads();
            cur ^= 1;
        }

        // ---- per-b epilogue: reduce, fc1
        #pragma unroll
        for (int o = 4; o <= 16; o <<= 1) {
            sacc0 += __shfl_xor_sync(0xffffffffu, sacc0, o);
            sacc1 += __shfl_xor_sync(0xffffffffu, sacc1, o);
        }
        if (lane < 4) {
            tsm[hb * 8 + lane * 2]     = sacc0;
            tsm[hb * 8 + lane * 2 + 1] = sacc1;
        }
        __syncthreads();
        if (tid < 32) {
            const float* wfc = (const float*)(smem + S_WFC);
            float u = ((const float*)(smem + S_FB))[tid];
            #pragma unroll 8
            for (int h = 0; h < HH; h++)
                u = fmaf(tsm[h], wfc[h * 32 + tid], u);
            g_u[b * 32 + tid] = u;
        }
        __syncthreads();

        b = ctl[(bi + 1) & 1];
        bi++;
    }

    // ===== Phase C: last CTA runs BatchNorm + LeakyReLU + fc2 inline =====
    __threadfence();
    if (tid == 0) {
        int old = atomicAdd(&g_done, 1);
        ctl[2] = (old == NCTA - 1) ? 1 : 0;
    }
    __syncthreads();
    if (!ctl[2]) return;

    // stage g_u into padded smem US[b][j] stride 33 (B image is dead here)
    float* US = (float*)(smem + SB);
    for (int i = tid; i < BB * 32; i += K1_THREADS)
        US[(i >> 5) * 33 + (i & 31)] = g_u[i];
    float* PS   = (float*)(smem + S_BUF0);       // [8][32] partials
    float* MEAN = PS + 256;                      // [32]
    float* RS   = MEAN + 32;                     // [32]
    __syncthreads();

    const int j = tid & 31, g = tid >> 5;        // 8 groups x 32 features
    {
        float s = 0.0f;
        #pragma unroll 8
        for (int bb = g * 64; bb < g * 64 + 64; bb++) s += US[bb * 33 + j];
        PS[g * 32 + j] = s;
    }
    __syncthreads();
    if (tid < 32) {
        float m = 0.0f;
        #pragma unroll
        for (int g2 = 0; g2 < 8; g2++) m += PS[g2 * 32 + tid];
        MEAN[tid] = m * (1.0f / (float)BB);
    }
    __syncthreads();
    {
        float mu = MEAN[j], s = 0.0f;
        #pragma unroll 8
        for (int bb = g * 64; bb < g * 64 + 64; bb++) {
            float d = US[bb * 33 + j] - mu;
            s += d * d;
        }
        PS[g * 32 + j] = s;
    }
    __syncthreads();
    if (tid < 32) {
        float v = 0.0f;
        #pragma unroll
        for (int g2 = 0; g2 < 8; g2++) v += PS[g2 * 32 + tid];
        RS[tid] = rsqrtf(v * (1.0f / (float)BB) + BN_EPS);
    }
    __syncthreads();

    for (int bb = tid; bb < BB; bb += K1_THREADS) {
        float a = __ldg(&fc2_b[0]);
        #pragma unroll
        for (int j2 = 0; j2 < 32; j2++) {
            float y = (US[bb * 33 + j2] - MEAN[j2]) * RS[j2] * __ldg(&gamma[j2]) + __ldg(&beta[j2]);
            a = fmaf(lrelu(y), __ldg(&fc2_w[j2]), a);
        }
        out[bb] = a;
    }

    // reset counters for next graph replay
    if (tid == 0) { g_ticket = 0; g_done = 0; }
}

// ---------------------------------------------------------------------------
extern "C" void kernel_launch(void* const* d_in, const int* in_sizes, int n_in,
                              void* d_out, int out_size) {
    const float* X     = (const float*)d_in[0];
    const float* Wc    = (const float*)d_in[1];
    const float* fc1_w = (const float*)d_in[2];
    const float* fc1_b = (const float*)d_in[3];
    const float* gamma = (const float*)d_in[4];
    const float* beta  = (const float*)d_in[5];
    const float* fc2_w = (const float*)d_in[6];
    const float* fc2_b = (const float*)d_in[7];
    float* out = (float*)d_out;

    cudaFuncSetAttribute(fused_all, cudaFuncAttributeMaxDynamicSharedMemorySize, SM_TOTAL);
    fused_all<<<NCTA, K1_THREADS, SM_TOTAL>>>(X, Wc, fc1_w, fc1_b,
                                              gamma, beta, fc2_w, fc2_b, out);
}

// round 8
// speedup vs baseline: 5.1300x; 1.0956x over previous
#include <cuda_runtime.h>
#include <cuda_fp16.h>
#include <cstdint>

// ---------------------------------------------------------------------------
// Problem constants
// ---------------------------------------------------------------------------
#define BB 512      // batch
#define SS 256      // set size
#define DD 64       // feature dim (K)
#define HH 64       // n_hidden_sets
#define EE 8        // n_elements
#define HE 512      // H*E (N of GEMM)
#define BN_EPS 1e-5f

#define NCTA 304          // 2 per SM on GB300 (152 SMs)
#define K1_THREADS 256

#define NCHUNK 4          // 256 rows / 64
#define CH_F4   1024      // float4 per chunk

// smem layout (bytes)
#define S_BUF0 0                    // X fp16 chunk buf 0 (8 KB)
#define S_BUF1 8192                 // X fp16 chunk buf 1 (8 KB)
#define SB     16384                // B fp16 image 64 KB (dead after frag load) | Phase C: US
#define S_TSM  83968                // T[64] floats
#define S_WFC  84224                // fc1_w transposed [h][j] 8 KB
#define S_FB   92416                // fc1_b [32]
#define S_CTL  92544                // control ints
#define SM_TOTAL 92608

// ---------------------------------------------------------------------------
// Device scratch (no dynamic allocation allowed)
// ---------------------------------------------------------------------------
__device__ float g_u[BB * 32];      // fc1 output
__device__ int   g_ticket = 0;      // persistent work queue
__device__ int   g_done   = 0;      // completion counter

__device__ __forceinline__ uint32_t smem_u32(const void* p) {
    uint32_t a;
    asm("{ .reg .u64 t; cvta.to.shared.u64 t, %1; cvt.u32.u64 %0, t; }" : "=r"(a) : "l"(p));
    return a;
}
__device__ __forceinline__ uint32_t swz(uint32_t off) {   // SW128: conflict-free ldmatrix
    return off ^ ((off >> 3) & 0x70);
}
__device__ __forceinline__ float lrelu(float x) { return fmaxf(x, 0.01f * x); }

__device__ __forceinline__ void ldsm_x4(uint32_t addr, uint32_t& r0, uint32_t& r1,
                                        uint32_t& r2, uint32_t& r3) {
    asm volatile("ldmatrix.sync.aligned.m8n8.x4.shared.b16 {%0,%1,%2,%3}, [%4];"
                 : "=r"(r0), "=r"(r1), "=r"(r2), "=r"(r3) : "r"(addr));
}
__device__ __forceinline__ void mma_fp16(float& c0, float& c1, float& c2, float& c3,
                                         uint32_t a0, uint32_t a1, uint32_t a2, uint32_t a3,
                                         uint32_t b0, uint32_t b1) {
    asm volatile("mma.sync.aligned.m16n8k16.row.col.f32.f16.f16.f32 "
                 "{%0,%1,%2,%3}, {%4,%5,%6,%7}, {%8,%9}, {%0,%1,%2,%3};"
                 : "+f"(c0), "+f"(c1), "+f"(c2), "+f"(c3)
                 : "r"(a0), "r"(a1), "r"(a2), "r"(a3), "r"(b0), "r"(b1));
}

// convert 4 float4 (one chunk's share) -> swizzled fp16 buffer (f16x2 pack cvt)
__device__ __forceinline__ void cvt_sts_chunk(char* smem, int bufoff, int tid,
                                              const float4* v) {
    #pragma unroll
    for (int j = 0; j < 4; j++) {
        int cc = tid + j * 256;            // float4 idx within chunk
        int row = cc >> 4, k4 = (cc & 15) << 2;
        __half2 p01 = __floats2half2_rn(v[j].x, v[j].y);
        __half2 p23 = __floats2half2_rn(v[j].z, v[j].w);
        uint32_t sw = swz((uint32_t)row * 128u + (uint32_t)k4 * 2u);
        *(uint2*)(smem + bufoff + sw) =
            make_uint2(*(uint32_t*)&p01, *(uint32_t*)&p23);
    }
}

// ---------------------------------------------------------------------------
// Single persistent kernel, chunk-pipelined
// ---------------------------------------------------------------------------
__global__ __launch_bounds__(K1_THREADS, 2)
void fused_all(const float* __restrict__ X, const float* __restrict__ Wc,
               const float* __restrict__ fc1_w, const float* __restrict__ fc1_b,
               const float* __restrict__ gamma, const float* __restrict__ beta,
               const float* __restrict__ fc2_w, const float* __restrict__ fc2_b,
               float* __restrict__ out) {
    extern __shared__ char smem[];
    const uint32_t sb = smem_u32(smem);
    const int tid  = threadIdx.x;
    const int hb   = tid >> 5;        // warp id == h-block
    const int lane = tid & 31;
    int* ctl = (int*)(smem + S_CTL);  // [0],[1]=ticket slots (parity), [2]=last flag

    // ===== Phase A: build B = Wc^T fp16 SW128 [n][k] image in smem (once) =====
    for (int i = tid; i < 16384; i += K1_THREADS) {
        int kk = i >> 9;               // k = 2*kk
        int n  = i & 511;
        float w0 = Wc[(2 * kk)     * HE + n];
        float w1 = Wc[(2 * kk + 1) * HE + n];
        __half2 h = __floats2half2_rn(w0, w1);
        uint32_t sw = swz((uint32_t)n * 128u + (uint32_t)kk * 4u);
        *(__half2*)(smem + SB + sw) = h;
    }
    for (int i = tid; i < 32 * HH; i += K1_THREADS) {
        int j = i >> 6, h = i & 63;
        ((float*)(smem + S_WFC))[h * 32 + j] = fc1_w[i];
    }
    if (tid < 32) ((float*)(smem + S_FB))[tid] = fc1_b[tid];
    if (tid == 0) ctl[0] = atomicAdd(&g_ticket, 1);
    __syncthreads();

    // ===== load all B fragments for this warp's h-block into registers (once)
    uint32_t bf[EE][8];
    #pragma unroll
    for (int e = 0; e < EE; e++) {
        #pragma unroll
        for (int half = 0; half < 2; half++) {
            uint32_t off = (uint32_t)(e * 64 + hb * 8 + (lane & 7)) * 128u
                         + (uint32_t)half * 64u + (uint32_t)(lane >> 3) * 16u;
            uint32_t sw = swz(off);
            ldsm_x4(sb + SB + sw, bf[e][half*4+0], bf[e][half*4+1],
                                   bf[e][half*4+2], bf[e][half*4+3]);
        }
    }

    // ===== Phase B: chunk-pipelined ticket loop =====
    float* tsm = (float*)(smem + S_TSM);
    int b = ctl[0];        // first ticket (written before the barrier above)
    int bi = 0;
    int cur = 0;

    // preload chunk 0 of first b
    {
        const float4* xsrc = (const float4*)(X + (size_t)b * SS * DD);
        float4 v[4];
        #pragma unroll
        for (int j = 0; j < 4; j++) v[j] = xsrc[tid + j * 256];
        cvt_sts_chunk(smem, S_BUF0, tid, v);
    }
    __syncthreads();

    while (b < BB) {
        float sacc0 = 0.0f, sacc1 = 0.0f;

        #pragma unroll
        for (int ch = 0; ch < NCHUNK; ch++) {
            // prefetch next ticket early (consumed at ch==3; syncs in between)
            if (ch == 0 && tid == 0) ctl[(bi + 1) & 1] = atomicAdd(&g_ticket, 1);

            // ---- issue LDG for next chunk (latency hidden behind MMAs)
            bool have_next = true;
            const float4* nsrc = nullptr;
            if (ch < NCHUNK - 1) {
                nsrc = (const float4*)(X + (size_t)b * SS * DD) + (ch + 1) * CH_F4;
            } else {
                int nb = ctl[(bi + 1) & 1];
                if (nb < BB) nsrc = (const float4*)(X + (size_t)nb * SS * DD);
                else have_next = false;
            }
            float4 v[4];
            if (have_next) {
                #pragma unroll
                for (int j = 0; j < 4; j++) v[j] = nsrc[tid + j * 256];
            }

            // ---- MMA over current chunk (4 m-tiles of 16 rows)
            const int bufoff = cur ? S_BUF1 : S_BUF0;
            #pragma unroll
            for (int q = 0; q < 4; q++) {
                const int m0 = q * 16;   // local row within chunk buffer
                float c[EE][4];
                #pragma unroll
                for (int e = 0; e < EE; e++)
                    #pragma unroll
                    for (int i = 0; i < 4; i++) c[e][i] = 0.0f;

                #pragma unroll
                for (int ks = 0; ks < 4; ks++) {
                    uint32_t off = (uint32_t)(m0 + (lane & 15)) * 128u
                                 + (uint32_t)ks * 32u + (uint32_t)(lane >> 4) * 16u;
                    uint32_t sw = swz(off);
                    uint32_t a0, a1, a2, a3;
                    ldsm_x4(sb + bufoff + sw, a0, a1, a2, a3);
                    const int i0 = (ks >> 1) * 4 + (ks & 1) * 2;
                    #pragma unroll
                    for (int e = 0; e < EE; e++)
                        mma_fp16(c[e][0], c[e][1], c[e][2], c[e][3],
                                 a0, a1, a2, a3, bf[e][i0], bf[e][i0+1]);
                }

                // max over E FIRST (lrelu is monotone -> commutes, exactly)
                float v0 = c[0][0], v1 = c[0][1], v2 = c[0][2], v3 = c[0][3];
                #pragma unroll
                for (int e = 1; e < EE; e++) {
                    v0 = fmaxf(v0, c[e][0]);
                    v1 = fmaxf(v1, c[e][1]);
                    v2 = fmaxf(v2, c[e][2]);
                    v3 = fmaxf(v3, c[e][3]);
                }
                sacc0 += lrelu(v0) + lrelu(v2);   // col h = hb*8 + (lane%4)*2
                sacc1 += lrelu(v1) + lrelu(v3);   // col h+1
            }

            // ---- convert + store next chunk into the other buffer
            if (have_next) cvt_sts_chunk(smem, cur ? S_BUF0 : S_BUF1, tid, v);
            __syncthreads();
            cur ^= 1;
        }

        // ---- per-b epilogue: reduce, fc1
        #pragma unroll
        for (int o = 4; o <= 16; o <<= 1) {
            sacc0 += __shfl_xor_sync(0xffffffffu, sacc0, o);
            sacc1 += __shfl_xor_sync(0xffffffffu, sacc1, o);
        }
        if (lane < 4) {
            tsm[hb * 8 + lane * 2]     = sacc0;
            tsm[hb * 8 + lane * 2 + 1] = sacc1;
        }
        __syncthreads();
        if (tid < 32) {
            const float* wfc = (const float*)(smem + S_WFC);
            float u = ((const float*)(smem + S_FB))[tid];
            #pragma unroll 8
            for (int h = 0; h < HH; h++)
                u = fmaf(tsm[h], wfc[h * 32 + tid], u);
            g_u[b * 32 + tid] = u;
        }
        __syncthreads();

        b = ctl[(bi + 1) & 1];
        bi++;
    }

    // ===== Phase C: last CTA runs BatchNorm + LeakyReLU + fc2 inline =====
    __threadfence();
    if (tid == 0) {
        int old = atomicAdd(&g_done, 1);
        ctl[2] = (old == NCTA - 1) ? 1 : 0;
    }
    __syncthreads();
    if (!ctl[2]) return;

    // stage g_u into padded smem US[b][j] stride 33 (B image is dead here)
    float* US = (float*)(smem + SB);
    for (int i = tid; i < BB * 32; i += K1_THREADS)
        US[(i >> 5) * 33 + (i & 31)] = g_u[i];
    float* PS   = (float*)(smem + S_BUF0);       // [8][32] partials
    float* MEAN = PS + 256;                      // [32]
    float* RS   = MEAN + 32;                     // [32]
    __syncthreads();

    const int j = tid & 31, g = tid >> 5;        // 8 groups x 32 features
    {
        float s = 0.0f;
        #pragma unroll 8
        for (int bb = g * 64; bb < g * 64 + 64; bb++) s += US[bb * 33 + j];
        PS[g * 32 + j] = s;
    }
    __syncthreads();
    if (tid < 32) {
        float m = 0.0f;
        #pragma unroll
        for (int g2 = 0; g2 < 8; g2++) m += PS[g2 * 32 + tid];
        MEAN[tid] = m * (1.0f / (float)BB);
    }
    __syncthreads();
    {
        float mu = MEAN[j], s = 0.0f;
        #pragma unroll 8
        for (int bb = g * 64; bb < g * 64 + 64; bb++) {
            float d = US[bb * 33 + j] - mu;
            s += d * d;
        }
        PS[g * 32 + j] = s;
    }
    __syncthreads();
    if (tid < 32) {
        float v = 0.0f;
        #pragma unroll
        for (int g2 = 0; g2 < 8; g2++) v += PS[g2 * 32 + tid];
        RS[tid] = rsqrtf(v * (1.0f / (float)BB) + BN_EPS);
    }
    __syncthreads();

    for (int bb = tid; bb < BB; bb += K1_THREADS) {
        float a = __ldg(&fc2_b[0]);
        #pragma unroll
        for (int j2 = 0; j2 < 32; j2++) {
            float y = (US[bb * 33 + j2] - MEAN[j2]) * RS[j2] * __ldg(&gamma[j2]) + __ldg(&beta[j2]);
            a = fmaf(lrelu(y), __ldg(&fc2_w[j2]), a);
        }
        out[bb] = a;
    }

    // reset counters for next graph replay
    if (tid == 0) { g_ticket = 0; g_done = 0; }
}

// ---------------------------------------------------------------------------
extern "C" void kernel_launch(void* const* d_in, const int* in_sizes, int n_in,
                              void* d_out, int out_size) {
    const float* X     = (const float*)d_in[0];
    const float* Wc    = (const float*)d_in[1];
    const float* fc1_w = (const float*)d_in[2];
    const float* fc1_b = (const float*)d_in[3];
    const float* gamma = (const float*)d_in[4];
    const float* beta  = (const float*)d_in[5];
    const float* fc2_w = (const float*)d_in[6];
    const float* fc2_b = (const float*)d_in[7];
    float* out = (float*)d_out;

    cudaFuncSetAttribute(fused_all, cudaFuncAttributeMaxDynamicSharedMemorySize, SM_TOTAL);
    fused_all<<<NCTA, K1_THREADS, SM_TOTAL>>>(X, Wc, fc1_w, fc1_b,
                                              gamma, beta, fc2_w, fc2_b, out);
}